// round 2
// baseline (speedup 1.0000x reference)
#include <cuda_runtime.h>
#include <math.h>

#define NN 100000
#define EE 600000
#define FF 128
#define CC 64
#define LT 8   // node tile in linear kernel

// ---------------- scratch (static __device__, no allocations) ----------------
__device__ float g_X0[(size_t)NN * FF];
__device__ float g_X1[(size_t)NN * FF];
__device__ float g_deg[NN];      // degree, then dinv in place
__device__ float g_norm[EE];     // ew, then norm in place
__device__ float g_s[FF];        // feature gate
__device__ int   g_is64;

// ---------------- dtype detection: int64 vs int32 edge_index ----------------
__global__ void k_detect(const int* __restrict__ w) {
    __shared__ int nz;
    if (threadIdx.x == 0) nz = 0;
    __syncthreads();
    int found = 0;
    for (int i = threadIdx.x; i < 1024; i += blockDim.x)
        if (w[2 * i + 1] != 0) found = 1;
    if (found) atomicOr(&nz, 1);
    __syncthreads();
    if (threadIdx.x == 0) g_is64 = nz ? 0 : 1;
}

__device__ __forceinline__ long long eidx(const void* p, long long i, int is64) {
    if (is64) return ((const long long*)p)[i];
    return (long long)((const int*)p)[i];
}

__device__ __forceinline__ float sigm(float w) {
    return 1.0f / (1.0f + __expf(-w));
}

// no-return vector reduction to global memory (REDG path, sm_90+)
__device__ __forceinline__ void red_add_v4(float* p, float4 v) {
    asm volatile("red.global.add.v4.f32 [%0], {%1, %2, %3, %4};"
                 :: "l"(p), "f"(v.x), "f"(v.y), "f"(v.z), "f"(v.w)
                 : "memory");
}

// ---------------- feature gate s[f] = sigmoid(xw[f]) * (|xw[f]|>0) -----------
__global__ void k_feat_gate(const float* __restrict__ xw) {
    int f = threadIdx.x;
    if (f < FF) {
        float w = xw[f];
        g_s[f] = (fabsf(w) > 0.0f) ? sigm(w) : 0.0f;
    }
}

// ---------------- X0 = x * s ; deg init = 1.0 (self loop) --------------------
__global__ void k_scale_x(const float* __restrict__ x) {
    int idx = blockIdx.x * blockDim.x + threadIdx.x;   // float4 index
    if (idx < NN * FF / 4) {
        float4 v = ((const float4*)x)[idx];
        int f = (idx & (FF / 4 - 1)) * 4;
        v.x *= g_s[f]; v.y *= g_s[f + 1]; v.z *= g_s[f + 2]; v.w *= g_s[f + 3];
        ((float4*)g_X0)[idx] = v;
        if (idx < NN) g_deg[idx] = 1.0f;
    }
}

// ---------------- per-edge weight + degree scatter ---------------------------
__global__ void k_edge_deg(const void* __restrict__ ei, const float* __restrict__ ew) {
    int e = blockIdx.x * blockDim.x + threadIdx.x;
    if (e < EE) {
        int is64 = g_is64;
        float w = ew[e];
        float s = (fabsf(w) > 0.0f) ? sigm(w) : 0.0f;
        g_norm[e] = s;
        long long c = eidx(ei, (long long)EE + e, is64);
        atomicAdd(&g_deg[c], s);
    }
}

// ---------------- dinv = rsqrt(deg); deg >= 1 always -------------------------
__global__ void k_dinv() {
    int i = blockIdx.x * blockDim.x + threadIdx.x;
    if (i < NN) g_deg[i] = rsqrtf(g_deg[i]);
}

// ---------------- norm[e] = dinv[row] * ew * dinv[col] -----------------------
__global__ void k_norm(const void* __restrict__ ei) {
    int e = blockIdx.x * blockDim.x + threadIdx.x;
    if (e < EE) {
        int is64 = g_is64;
        long long r = eidx(ei, e, is64);
        long long c = eidx(ei, (long long)EE + e, is64);
        g_norm[e] = g_deg[r] * g_norm[e] * g_deg[c];
    }
}

// ---------------- self-loop term: dst[i] = dinv[i]^2 * src[i] ----------------
__global__ void k_self(int dir) {
    const float* src = dir ? g_X1 : g_X0;
    float*       dst = dir ? g_X0 : g_X1;
    int idx = blockIdx.x * blockDim.x + threadIdx.x;   // float4 index
    if (idx < NN * FF / 4) {
        int i = idx >> 5;                               // / (FF/4)
        float d = g_deg[i];
        float dd = d * d;
        float4 v = ((const float4*)src)[idx];
        v.x *= dd; v.y *= dd; v.z *= dd; v.w *= dd;
        ((float4*)dst)[idx] = v;
    }
}

// ---------------- edge scatter: dst[col] += norm * src[row] ------------------
// one thread per (edge, float4): 32 threads share an edge (broadcast loads).
__global__ void k_prop(const void* __restrict__ ei, int dir) {
    const float* src = dir ? g_X1 : g_X0;
    float*       dst = dir ? g_X0 : g_X1;
    int t = blockIdx.x * blockDim.x + threadIdx.x;
    if (t < EE * 32) {
        int e = t >> 5;
        int lane = t & 31;
        float nrm = g_norm[e];
        int is64 = g_is64;
        long long r = eidx(ei, e, is64);
        long long c = eidx(ei, (long long)EE + e, is64);
        float4 v = ((const float4*)(src + r * FF))[lane];
        v.x *= nrm; v.y *= nrm; v.z *= nrm; v.w *= nrm;
        red_add_v4(((float*)(dst + c * FF)) + lane * 4, v);
    }
}

// ---------------- out = log_softmax(X @ W^T + b) -----------------------------
// block = 64 threads (one class each), 8-node tile, W cached in padded smem.
__global__ void k_linear(const float* __restrict__ W, const float* __restrict__ b,
                         float* __restrict__ out) {
    __shared__ float4 sW[CC * 33];        // row pad 33 float4 -> conflict-free
    __shared__ float  sx[LT][FF];
    __shared__ float  redm[2], reds[2];
    const float* X = g_X0;                // result of hop 2
    int tid = threadIdx.x;                // 0..63 == class
    for (int i = tid; i < CC * FF / 4; i += CC) {
        int c = i >> 5;
        int k4 = i & 31;
        sW[c * 33 + k4] = ((const float4*)W)[i];
    }
    float bias = b[tid];
    __syncthreads();

    for (int g = blockIdx.x; g < NN / LT; g += gridDim.x) {
        long long base = (long long)g * LT;
        for (int i = tid; i < LT * FF / 4; i += CC)
            ((float4*)&sx[0][0])[i] = ((const float4*)(X + base * FF))[i];
        __syncthreads();

        float acc[LT];
        #pragma unroll
        for (int t2 = 0; t2 < LT; t2++) acc[t2] = bias;
        const float4* wr = &sW[tid * 33];
        #pragma unroll
        for (int k4 = 0; k4 < FF / 4; k4++) {
            float4 w4 = wr[k4];
            #pragma unroll
            for (int t2 = 0; t2 < LT; t2++) {
                float4 x4 = ((const float4*)sx[t2])[k4];
                acc[t2] += w4.x * x4.x + w4.y * x4.y + w4.z * x4.z + w4.w * x4.w;
            }
        }

        #pragma unroll
        for (int t2 = 0; t2 < LT; t2++) {
            float v = acc[t2];
            float m = v;
            #pragma unroll
            for (int o = 16; o > 0; o >>= 1)
                m = fmaxf(m, __shfl_xor_sync(0xffffffffu, m, o));
            if ((tid & 31) == 0) redm[tid >> 5] = m;
            __syncthreads();
            m = fmaxf(redm[0], redm[1]);
            float ex = __expf(v - m);
            float ssum = ex;
            #pragma unroll
            for (int o = 16; o > 0; o >>= 1)
                ssum += __shfl_xor_sync(0xffffffffu, ssum, o);
            if ((tid & 31) == 0) reds[tid >> 5] = ssum;
            __syncthreads();
            float tot = reds[0] + reds[1];
            out[(base + t2) * CC + tid] = v - m - __logf(tot);
        }
        __syncthreads();   // protect sx / redm before next tile
    }
}

// ---------------------------------------------------------------------------
extern "C" void kernel_launch(void* const* d_in, const int* in_sizes, int n_in,
                              void* d_out, int out_size) {
    const float* x  = (const float*)d_in[0];
    const void*  ei = d_in[1];
    const float* ew = (const float*)d_in[2];
    const float* xw = (const float*)d_in[3];
    const float* W  = (const float*)d_in[4];
    const float* b  = (const float*)d_in[5];
    float* out = (float*)d_out;

    const int THREADS = 256;
    const int nxf4 = NN * FF / 4;

    k_detect<<<1, 256>>>((const int*)ei);
    k_feat_gate<<<1, 128>>>(xw);
    k_scale_x<<<(nxf4 + THREADS - 1) / THREADS, THREADS>>>(x);
    k_edge_deg<<<(EE + THREADS - 1) / THREADS, THREADS>>>(ei, ew);
    k_dinv<<<(NN + THREADS - 1) / THREADS, THREADS>>>();
    k_norm<<<(EE + THREADS - 1) / THREADS, THREADS>>>(ei);

    // hop 1: X0 -> X1
    k_self<<<(nxf4 + THREADS - 1) / THREADS, THREADS>>>(0);
    k_prop<<<(EE * 32 + THREADS - 1) / THREADS, THREADS>>>(ei, 0);
    // hop 2: X1 -> X0
    k_self<<<(nxf4 + THREADS - 1) / THREADS, THREADS>>>(1);
    k_prop<<<(EE * 32 + THREADS - 1) / THREADS, THREADS>>>(ei, 1);

    k_linear<<<1480, CC>>>(W, b, out);
}